// round 17
// baseline (speedup 1.0000x reference)
#include <cuda_runtime.h>
#include <cuda_fp16.h>
#include <math.h>
#include <stdint.h>

#define B_   2048
#define S_   61
#define D_   768
#define H_   512
#define L_   23
#define MTOT (B_ * S_)   // 124928 = 976 * 128

#define HEAD_TOK 1
#define TAIL_TOK 2

// ---------------- scratch globals (no allocation allowed) -------------------
__device__ float  g_buf[MTOT];
__device__ __half W1h[H_ * D_];

// ---------------- helpers ----------------------------------------------------
__device__ __forceinline__ uint32_t smem_u32(const void* p) {
    uint32_t a;
    asm("{ .reg .u64 t; cvta.to.shared.u64 t, %1; cvt.u32.u64 %0, t; }"
        : "=r"(a) : "l"(p));
    return a;
}
__device__ __forceinline__ void cp16(uint32_t dst, const void* src) {
    asm volatile("cp.async.cg.shared.global [%0], [%1], 16;"
                 :: "r"(dst), "l"(src) : "memory");
}
__device__ __forceinline__ void ldsm4(uint32_t* d, uint32_t addr) {
    asm volatile("ldmatrix.sync.aligned.m8n8.x4.shared.b16 {%0,%1,%2,%3}, [%4];"
                 : "=r"(d[0]), "=r"(d[1]), "=r"(d[2]), "=r"(d[3]) : "r"(addr));
}
__device__ __forceinline__ void mma16816(float* c, const uint32_t* a,
                                         uint32_t b0, uint32_t b1) {
    asm volatile(
        "mma.sync.aligned.m16n8k16.row.col.f32.f16.f16.f32 "
        "{%0,%1,%2,%3}, {%4,%5,%6,%7}, {%8,%9}, {%0,%1,%2,%3};"
        : "+f"(c[0]), "+f"(c[1]), "+f"(c[2]), "+f"(c[3])
        : "r"(a[0]), "r"(a[1]), "r"(a[2]), "r"(a[3]), "r"(b0), "r"(b1));
}

// ---------------------------------------------------------------------------
// prep_kernel: W1 fp32 -> fp16
// ---------------------------------------------------------------------------
__global__ void prep_kernel(const float* __restrict__ W1) {
    int i = blockIdx.x * 256 + threadIdx.x;          // over H_*D_/4 float4s
    float4 x = reinterpret_cast<const float4*>(W1)[i];
    __half2 h0 = make_half2(__float2half(x.x), __float2half(x.y));
    __half2 h1 = make_half2(__float2half(x.z), __float2half(x.w));
    uint2 hp = make_uint2(*reinterpret_cast<uint32_t*>(&h0),
                          *reinterpret_cast<uint32_t*>(&h1));
    *reinterpret_cast<uint2*>(&W1h[4 * (size_t)i]) = hp;
}

// ---------------------------------------------------------------------------
// gate_kernel: single-pass fp16 HMMA fused gate GEMM, depth-2 A pipeline
//   H[128,512] = Vtile[128,768] @ W1^T ; g = w2 . tanh(H + b1) + b2
// 256 threads, 8 warps (2m x 4n); warp tile m64 x n32 (4 mt x 4 nt).
// 4 N-chunks of 128; 12 K-stages of 64, double-buffered smem.
// Stage s top: convert areg(A for s+1)->smem, issue B(s+1) cp.async,
// issue LDG A(s+2); then MMA(s); tail = wait+sync only.
// ---------------------------------------------------------------------------
#define RS      144                  // smem row stride bytes (64 fp16 + 16B pad)
#define ABYTES  (128 * RS)           // 18432 per matrix
#define BUFB    (2 * ABYTES)         // A, B = 36864 per stage
#define OFF_W2  0
#define OFF_B1  2048
#define OFF_GS  4096                 // 512 floats
#define OFF_BUF 8192
#define GATE_SMEM (OFF_BUF + 2 * BUFB)   // 81920

__device__ __forceinline__ void lda_tile(float4* areg, const float* __restrict__ V,
                                         int row0, int k0, int tid) {
#pragma unroll
    for (int it = 0; it < 8; ++it) {
        int v = tid + it * 256, r = v >> 4, c4 = v & 15;
        areg[it] = *reinterpret_cast<const float4*>(
            V + (size_t)(row0 + r) * D_ + k0 + c4 * 4);
    }
}
__device__ __forceinline__ void cvt_sts(char* base, const float4* areg, int tid) {
#pragma unroll
    for (int it = 0; it < 8; ++it) {
        int v = tid + it * 256, r = v >> 4, c4 = v & 15;
        __half2 p0 = make_half2(__float2half(areg[it].x), __float2half(areg[it].y));
        __half2 p1 = make_half2(__float2half(areg[it].z), __float2half(areg[it].w));
        uint2 hp = make_uint2(*reinterpret_cast<uint32_t*>(&p0),
                              *reinterpret_cast<uint32_t*>(&p1));
        *reinterpret_cast<uint2*>(base + r * RS + c4 * 8) = hp;
    }
}
__device__ __forceinline__ void ldb_tile(uint32_t dst, int n0, int k0, int tid) {
#pragma unroll
    for (int it = 0; it < 4; ++it) {
        int v = tid + it * 256, r = v >> 3, j = v & 7;
        cp16(dst + (uint32_t)(r * RS + j * 16),
             W1h + (size_t)(n0 + r) * D_ + k0 + j * 8);
    }
}

__global__ __launch_bounds__(256, 1)
void gate_kernel(const float* __restrict__ V,
                 const float* __restrict__ B1,
                 const float* __restrict__ W2,
                 const float* __restrict__ B2)
{
    extern __shared__ char sm[];
    const uint32_t sb = smem_u32(sm);
    const int tid  = threadIdx.x;
    const int wid  = tid >> 5;
    const int lane = tid & 31;
    const int wm   = wid >> 2;       // 0..1  (m direction, 64 rows each)
    const int wn   = wid & 3;        // 0..3  (n direction, 32 cols each)
    const int row0 = blockIdx.x * 128;

    float* w2s = reinterpret_cast<float*>(sm + OFF_W2);
    float* b1s = reinterpret_cast<float*>(sm + OFF_B1);
    float* gs  = reinterpret_cast<float*>(sm + OFF_GS);

    for (int i = tid; i < H_; i += 256) { w2s[i] = W2[i]; b1s[i] = B1[i]; }
    for (int i = tid; i < 512; i += 256) gs[i] = 0.0f;
    __syncthreads();

    // ldmatrix per-thread address components
    const int a_m  = (lane & 7) + ((lane >> 3) & 1) * 8;
    const int a_k2 = (lane >> 4) * 16;
    const int b_n  = (lane & 7) + (lane >> 4) * 8;
    const int b_k2 = ((lane >> 3) & 1) * 16;
    const uint32_t aoff = (uint32_t)((wm * 64 + a_m) * RS) + (uint32_t)a_k2;
    const uint32_t boff = (uint32_t)((wn * 32 + b_n) * RS) + (uint32_t)b_k2;

    float4 areg[8];

#pragma unroll 1
    for (int nc = 0; nc < 4; ++nc) {
        const int n0 = nc * 128;
        float c[4][4][4];
#pragma unroll
        for (int mt = 0; mt < 4; ++mt)
#pragma unroll
            for (int nt = 0; nt < 4; ++nt)
#pragma unroll
                for (int e = 0; e < 4; ++e) c[mt][nt][e] = 0.0f;

        // ---- prologue: B(0), A(0) convert, A(1) prefetch ----
        ldb_tile(sb + OFF_BUF + (uint32_t)ABYTES, n0, 0, tid);
        asm volatile("cp.async.commit_group;" ::: "memory");
        lda_tile(areg, V, row0, 0, tid);
        cvt_sts(sm + OFF_BUF, areg, tid);
        lda_tile(areg, V, row0, 64, tid);            // A for stage 1
        asm volatile("cp.async.wait_group 0;" ::: "memory");
        __syncthreads();

        // ---- main loop over 12 K-stages ----
#pragma unroll 1
        for (int s = 0; s < 12; ++s) {
            const uint32_t curBuf = OFF_BUF + (uint32_t)(s & 1) * BUFB;
            const uint32_t nxtBuf = OFF_BUF + (uint32_t)((s + 1) & 1) * BUFB;

            if (s < 11) {
                // stage-top: stage A(s+1) (loaded last stage) into smem
                cvt_sts(sm + nxtBuf, areg, tid);
                // B(s+1)
                ldb_tile(sb + nxtBuf + (uint32_t)ABYTES, n0, (s + 1) * 64, tid);
                asm volatile("cp.async.commit_group;" ::: "memory");
            }
            if (s < 10) {
                // prefetch A(s+2) into regs (consumed at s+1 top)
                lda_tile(areg, V, row0, (s + 2) * 64, tid);
            }

            // ---- compute 4 x k16 from current buffers ----
            const uint32_t Ah = sb + curBuf;
            const uint32_t Bh = sb + curBuf + (uint32_t)ABYTES;
#pragma unroll
            for (int kk = 0; kk < 4; ++kk) {
                const uint32_t kb = (uint32_t)(kk * 32);
                uint32_t ah[4][4];
#pragma unroll
                for (int mt = 0; mt < 4; ++mt)
                    ldsm4(ah[mt], Ah + aoff + (uint32_t)(mt * 16 * RS) + kb);
                uint32_t bh[2][4];
#pragma unroll
                for (int p = 0; p < 2; ++p)
                    ldsm4(bh[p], Bh + boff + (uint32_t)(p * 16 * RS) + kb);
#pragma unroll
                for (int mt = 0; mt < 4; ++mt)
#pragma unroll
                    for (int nt = 0; nt < 4; ++nt)
                        mma16816(c[mt][nt], ah[mt],
                                 bh[nt >> 1][(nt & 1) * 2], bh[nt >> 1][(nt & 1) * 2 + 1]);
            }

            if (s < 11) {
                asm volatile("cp.async.wait_group 0;" ::: "memory");
            }
            __syncthreads();
        }

        // ---- epilogue: accumulate partial g into gs ----
#pragma unroll
        for (int mt = 0; mt < 4; ++mt) {
            float s0 = 0.0f, s1 = 0.0f;
#pragma unroll
            for (int nt = 0; nt < 4; ++nt) {
                int n = nc * 128 + wn * 32 + nt * 8 + (lane & 3) * 2;
                float w0 = w2s[n],     w1v = w2s[n + 1];
                float q0 = b1s[n],     q1  = b1s[n + 1];
                s0 += w0 * tanhf(c[mt][nt][0] + q0) + w1v * tanhf(c[mt][nt][1] + q1);
                s1 += w0 * tanhf(c[mt][nt][2] + q0) + w1v * tanhf(c[mt][nt][3] + q1);
            }
            s0 += __shfl_xor_sync(0xffffffffu, s0, 1);
            s0 += __shfl_xor_sync(0xffffffffu, s0, 2);
            s1 += __shfl_xor_sync(0xffffffffu, s1, 1);
            s1 += __shfl_xor_sync(0xffffffffu, s1, 2);
            if ((lane & 3) == 0) {
                int m = wm * 64 + mt * 16 + (lane >> 2);
                gs[wn * 128 + m]     += s0;
                gs[wn * 128 + m + 8] += s1;
            }
        }
    }

    __syncthreads();
    if (tid < 128)
        g_buf[row0 + tid] = gs[tid] + gs[128 + tid] + gs[256 + tid] + gs[384 + tid]
                          + B2[0];
}

// ---------------------------------------------------------------------------
// attn_kernel: single-pass online softmax. 256 threads / 8 warps; each warp
// owns key rows k = warp, warp+8, ...; V is read from DRAM exactly once.
// Uses ms == 1/61 identity to skip the first softmax.
// ---------------------------------------------------------------------------
__global__ __launch_bounds__(256)
void attn_kernel(const float* __restrict__ T,
                 const float* __restrict__ V,
                 const int*   __restrict__ ids,
                 const float* __restrict__ CW,
                 const float* __restrict__ CB,
                 float*       __restrict__ out)
{
    __shared__ float Th[D_], Tt[D_];
    __shared__ float enth[D_], entt[D_];
    __shared__ float gsh[S_ + 3];
    __shared__ float mwh[8], swh[8], mwt[8], swt[8];
    __shared__ int   hidx, tidx;

    const int b    = blockIdx.x;
    const int tid  = threadIdx.x;
    const int warp = tid >> 5, lane = tid & 31;

    if (tid == 0) { hidx = 0; tidx = 0; }
    __syncthreads();

    if (tid < S_) {
        int id = ids[b * S_ + tid];
        if (id == HEAD_TOK) hidx = tid;
        if (id == TAIL_TOK) tidx = tid;
        gsh[tid] = g_buf[b * S_ + tid];
    }
    __syncthreads();

    const int hq = hidx, tq = tidx;
    for (int d = tid; d < D_; d += 256) {
        Th[d] = T[((size_t)b * S_ + hq) * D_ + d];
        Tt[d] = T[((size_t)b * S_ + tq) * D_ + d];
        enth[d] = 0.0f;
        entt[d] = 0.0f;
    }
    __syncthreads();

    const float scale = sqrtf((float)D_);
    const float inv61 = 1.0f / (float)S_;

    float acch[24], acct[24];
#pragma unroll
    for (int j = 0; j < 24; ++j) { acch[j] = 0.0f; acct[j] = 0.0f; }
    float mh = -1e30f, sh = 0.0f;
    float mt = -1e30f, st = 0.0f;

    for (int k = warp; k < S_; k += 8) {
        const float* vr = V + ((size_t)b * S_ + k) * D_;
        float v[24];
#pragma unroll
        for (int j = 0; j < 24; ++j) v[j] = vr[lane + 32 * j];

        float dh = 0.0f, dt = 0.0f;
#pragma unroll
        for (int j = 0; j < 24; ++j) {
            dh = fmaf(Th[lane + 32 * j], v[j], dh);
            dt = fmaf(Tt[lane + 32 * j], v[j], dt);
        }
#pragma unroll
        for (int o = 16; o; o >>= 1) {
            dh += __shfl_xor_sync(0xffffffffu, dh, o);
            dt += __shfl_xor_sync(0xffffffffu, dt, o);
        }

        float gk = gsh[k];
        float ah = (dh * (1.0f - gk) + gk * inv61) / scale;
        float at = (dt * (1.0f - gk) + gk * inv61) / scale;

        // head online update
        float mn  = fmaxf(mh, ah);
        float scl = expf(mh - mn);
        float e   = expf(ah - mn);
        sh = sh * scl + e;
#pragma unroll
        for (int j = 0; j < 24; ++j) acch[j] = fmaf(acch[j], scl, e * v[j]);
        mh = mn;

        // tail online update
        mn  = fmaxf(mt, at);
        scl = expf(mt - mn);
        e   = expf(at - mn);
        st = st * scl + e;
#pragma unroll
        for (int j = 0; j < 24; ++j) acct[j] = fmaf(acct[j], scl, e * v[j]);
        mt = mn;
    }

    if (lane == 0) { mwh[warp] = mh; swh[warp] = sh; mwt[warp] = mt; swt[warp] = st; }
    __syncthreads();

    float Mh = -1e30f, Mt = -1e30f;
#pragma unroll
    for (int w = 0; w < 8; ++w) {
        Mh = fmaxf(Mh, mwh[w]);
        Mt = fmaxf(Mt, mwt[w]);
    }
    float Sh = 0.0f, St = 0.0f;
#pragma unroll
    for (int w = 0; w < 8; ++w) {
        Sh += swh[w] * expf(mwh[w] - Mh);
        St += swt[w] * expf(mwt[w] - Mt);
    }
    const float fh = expf(mh - Mh) / Sh;
    const float ft = expf(mt - Mt) / St;

#pragma unroll
    for (int j = 0; j < 24; ++j) {
        atomicAdd(&enth[lane + 32 * j], acch[j] * fh);
        atomicAdd(&entt[lane + 32 * j], acct[j] * ft);
    }
    __syncthreads();

    // classifier: logits[l] = clf_w[l] . [enth, entt] + clf_b[l]
    for (int l = warp; l < L_; l += 8) {
        const float* cw = CW + (size_t)l * (2 * D_);
        float s = 0.0f;
#pragma unroll
        for (int j = 0; j < 24; ++j) {
            int d = lane + 32 * j;
            s = fmaf(cw[d],       enth[d], s);
            s = fmaf(cw[D_ + d],  entt[d], s);
        }
#pragma unroll
        for (int o = 16; o; o >>= 1) s += __shfl_xor_sync(0xffffffffu, s, o);
        if (lane == 0) out[(size_t)b * L_ + l] = s + CB[l];
    }
}

// ---------------------------------------------------------------------------
extern "C" void kernel_launch(void* const* d_in, const int* in_sizes, int n_in,
                              void* d_out, int out_size)
{
    const float* T_recon = (const float*)d_in[0];
    const float* V_recon = (const float*)d_in[1];
    const int*   ids     = (const int*)  d_in[2];
    const float* fc1_w   = (const float*)d_in[3];
    const float* fc1_b   = (const float*)d_in[4];
    const float* fc2_w   = (const float*)d_in[5];
    const float* fc2_b   = (const float*)d_in[6];
    const float* clf_w   = (const float*)d_in[7];
    const float* clf_b   = (const float*)d_in[8];
    float* out = (float*)d_out;

    cudaFuncSetAttribute(gate_kernel,
                         cudaFuncAttributeMaxDynamicSharedMemorySize, GATE_SMEM);

    prep_kernel<<<H_ * D_ / 4 / 256, 256>>>(fc1_w);
    gate_kernel<<<MTOT / 128, 256, GATE_SMEM>>>(V_recon, fc1_b, fc2_w, fc2_b);
    attn_kernel<<<B_, 256>>>(T_recon, V_recon, ids, clf_w, clf_b, out);
}